// round 2
// baseline (speedup 1.0000x reference)
#include <cuda_runtime.h>

typedef unsigned long long ull;

#define SEQ   1024
#define NBH   64
#define LOG2E 1.4426950408889634f

// rel_h / rel_w logit tables, pre-scaled by log2(e): [bh][s][k], k in 0..31
__device__ __align__(16) float g_relH[(size_t)NBH * SEQ * 32];
__device__ __align__(16) float g_relW[(size_t)NBH * SEQ * 32];

// ---------- f32x2 helpers ----------
__device__ __forceinline__ ull pack2(float x, float y) {
    ull r; asm("mov.b64 %0, {%1,%2};" : "=l"(r) : "f"(x), "f"(y)); return r;
}
__device__ __forceinline__ void unpack2(ull p, float& x, float& y) {
    asm("mov.b64 {%0,%1}, %2;" : "=f"(x), "=f"(y) : "l"(p));
}
__device__ __forceinline__ void fma2(ull& d, ull a, ull b) {
    asm("fma.rn.f32x2 %0, %1, %2, %0;" : "+l"(d) : "l"(a), "l"(b));
}
__device__ __forceinline__ ull mul2(ull a, ull b) {
    ull r; asm("mul.rn.f32x2 %0, %1, %2;" : "=l"(r) : "l"(a), "l"(b)); return r;
}
__device__ __forceinline__ float ex2f(float x) {
    float r; asm("ex2.approx.f32 %0, %1;" : "=f"(r) : "f"(x)); return r;
}

// ---------- kernel A: rel_h / rel_w precompute (smem-staged, tiled) ----------
// grid: (32 h-values, 64 bh), 256 threads.
// For block (bh, h): rows s = h*32 + w, w = 0..31.
//   rel_h[s][k] = q[s] . rph[h + 31 - k]
//   rel_w[s][k] = q[s] . rpw[w + 31 - k]
__global__ void __launch_bounds__(256) rel_kernel(
    const float* __restrict__ q,
    const float* __restrict__ rph,
    const float* __restrict__ rpw)
{
    __shared__ float sQ[32 * 68];
    __shared__ float sRh[32 * 68];
    __shared__ float sRw[63 * 68];

    const int tid = threadIdx.x;
    const int h  = blockIdx.x;
    const int bh = blockIdx.y;
    const int b = bh >> 4, hd = bh & 15;

    {
        const int w = tid >> 3, c0 = (tid & 7) * 8;
        const float4* src = (const float4*)(q + ((size_t)(b * SEQ + h * 32 + w) * 16 + hd) * 64 + c0);
        *(float4*)(sQ + w * 68 + c0)     = src[0];
        *(float4*)(sQ + w * 68 + c0 + 4) = src[1];
        const float4* hs = (const float4*)(rph + (size_t)(h + 31 - w) * 64 + c0);
        *(float4*)(sRh + w * 68 + c0)     = hs[0];
        *(float4*)(sRh + w * 68 + c0 + 4) = hs[1];
    }
    for (int i = tid; i < 63 * 16; i += 256) {
        int r = i >> 4, c = (i & 15) * 4;
        *(float4*)(sRw + r * 68 + c) = *(const float4*)(rpw + (size_t)r * 64 + c);
    }
    __syncthreads();

    const int wid = tid >> 5, lane = tid & 31;   // lane = k
    #pragma unroll
    for (int rr = 0; rr < 4; rr++) {
        const int w = wid * 4 + rr;
        const float4* qv = (const float4*)(sQ + w * 68);
        const float4* hv = (const float4*)(sRh + lane * 68);
        const float4* wv = (const float4*)(sRw + (w + 31 - lane) * 68);
        float ah = 0.f, aw = 0.f;
        #pragma unroll
        for (int f = 0; f < 16; f++) {
            float4 a = qv[f], x = hv[f], y = wv[f];
            ah += a.x * x.x + a.y * x.y + a.z * x.z + a.w * x.w;
            aw += a.x * y.x + a.y * y.y + a.z * y.z + a.w * y.w;
        }
        size_t o = ((size_t)bh * SEQ + h * 32 + w) * 32 + lane;
        g_relH[o] = ah * LOG2E;
        g_relW[o] = aw * LOG2E;
    }
}

// ---------- kernel B: fp32 flash attention, 8x8 thread tiles, f32x2 FMAs ----
// grid: (16 m-tiles, 64 heads), block: 64 threads (tx 0..7 over n/d, ty 0..7 over m)
// thread tile: 8 rows x 8 cols. S paired over m; O paired over d.
// smem strides: Qt 68 (vector), KP 65 (scalar, bank-clean), Vs 68 (vector).
#define QT_S 68
#define KP_S 65
#define VS_S 68

__global__ void __launch_bounds__(64, 3)
flash_kernel(const float* __restrict__ q, const float* __restrict__ k,
             const float* __restrict__ v, float* __restrict__ out)
{
    extern __shared__ float sm[];
    float* Qt = sm;                     // [64][68]  Qt[c][m], scaled by 0.125*log2e
    float* KP = Qt + 64 * QT_S;         // [64][65]  Kt[c][n] during QK, P[m][n] during PV
    float* Vs = KP + 64 * KP_S;         // [64][68]  V[n][d]
    float* rH = Vs + 64 * VS_S;         // [64][32]
    float* rW = rH + 64 * 32;           // [64][32]

    const int tid = threadIdx.x;
    const int tx = tid & 7, ty = tid >> 3;
    const int mrow = ty * 8;
    const int m0 = blockIdx.x << 6;
    const int bh = blockIdx.y;
    const int b = bh >> 4, hd = bh & 15;

    const size_t hoff = (size_t)b * SEQ * 1024 + (size_t)hd * 64;
    const float* qh = q + hoff;
    const float* kh = k + hoff;
    const float* vh = v + hoff;
    float*       oh = out + hoff;

    // ---- load Q tile transposed (scaled) + rel tables ----
    {
        const float qs = 0.125f * LOG2E;
        const float4* src = (const float4*)(qh + (size_t)(m0 + tid) * 1024);
        #pragma unroll
        for (int f = 0; f < 16; f++) {
            float4 x = src[f];
            Qt[(4 * f + 0) * QT_S + tid] = x.x * qs;
            Qt[(4 * f + 1) * QT_S + tid] = x.y * qs;
            Qt[(4 * f + 2) * QT_S + tid] = x.z * qs;
            Qt[(4 * f + 3) * QT_S + tid] = x.w * qs;
        }
        const float4* rh4 = (const float4*)(g_relH + ((size_t)bh * SEQ + m0) * 32);
        const float4* rw4 = (const float4*)(g_relW + ((size_t)bh * SEQ + m0) * 32);
        #pragma unroll
        for (int f = 0; f < 8; f++) {
            ((float4*)rH)[tid + f * 64] = rh4[tid + f * 64];
            ((float4*)rW)[tid + f * 64] = rw4[tid + f * 64];
        }
    }

    ull   Oa[8][4];                 // O accumulator: 8 m-rows x 4 d-pairs
    float rowm[8], rowl[8];
    #pragma unroll
    for (int r = 0; r < 8; r++) {
        Oa[r][0] = 0ull; Oa[r][1] = 0ull; Oa[r][2] = 0ull; Oa[r][3] = 0ull;
        rowm[r] = -3.0e38f; rowl[r] = 0.f;
    }

    const int khbase = tx >> 2;          // (tx*8)/32
    const int kwoff  = (tx & 3) * 8;     // (tx*8) mod 32

    for (int n0 = 0; n0 < SEQ; n0 += 64) {
        __syncthreads();   // prev PV done reading KP/Vs (iter 0: Qt/rel stores)
        // ---- load K transposed (stride 65) + V natural (stride 68) ----
        {
            const float4* ks  = (const float4*)(kh + (size_t)(n0 + tid) * 1024);
            const float4* vs4 = (const float4*)(vh + (size_t)(n0 + tid) * 1024);
            float* vd = Vs + tid * VS_S;
            #pragma unroll
            for (int f = 0; f < 16; f++) {
                float4 kx = ks[f];
                KP[(4 * f + 0) * KP_S + tid] = kx.x;
                KP[(4 * f + 1) * KP_S + tid] = kx.y;
                KP[(4 * f + 2) * KP_S + tid] = kx.z;
                KP[(4 * f + 3) * KP_S + tid] = kx.w;
                *(float4*)(vd + 4 * f) = vs4[f];
            }
        }
        __syncthreads();

        // ---- S = Qs K^T : 8x8 tile, f32x2 paired over m ----
        ull Sa[4][8];
        #pragma unroll
        for (int i = 0; i < 4; i++)
            #pragma unroll
            for (int j = 0; j < 8; j++) Sa[i][j] = 0ull;

        #pragma unroll 4
        for (int c = 0; c < 64; c++) {
            const ull* qp = (const ull*)(Qt + c * QT_S + mrow);
            ull a0 = qp[0], a1 = qp[1], a2 = qp[2], a3 = qp[3];
            const float* kp = KP + c * KP_S + tx * 8;
            #pragma unroll
            for (int j = 0; j < 8; j++) {
                float bv = kp[j];
                ull bb = pack2(bv, bv);
                fma2(Sa[0][j], a0, bb);
                fma2(Sa[1][j], a1, bb);
                fma2(Sa[2][j], a2, bb);
                fma2(Sa[3][j], a3, bb);
            }
        }

        __syncthreads();   // all threads done reading KP as K

        // ---- streamed softmax (2 rows at a time) + P store into KP ----
        const int khid = (n0 >> 5) + khbase;
        #pragma unroll
        for (int i = 0; i < 4; i++) {
            float s0[8], s1[8];
            #pragma unroll
            for (int j = 0; j < 8; j++) unpack2(Sa[i][j], s0[j], s1[j]);
            const int R0 = mrow + 2 * i, R1 = R0 + 1;
            const float rh0 = rH[R0 * 32 + khid];
            const float rh1 = rH[R1 * 32 + khid];
            const float* w0 = rW + R0 * 32 + kwoff;
            const float* w1 = rW + R1 * 32 + kwoff;
            #pragma unroll
            for (int j = 0; j < 8; j++) {
                s0[j] += rh0 + w0[j];
                s1[j] += rh1 + w1[j];
            }
            float mx0 = s0[0], mx1 = s1[0];
            #pragma unroll
            for (int j = 1; j < 8; j++) { mx0 = fmaxf(mx0, s0[j]); mx1 = fmaxf(mx1, s1[j]); }
            mx0 = fmaxf(mx0, __shfl_xor_sync(0xffffffffu, mx0, 1));
            mx0 = fmaxf(mx0, __shfl_xor_sync(0xffffffffu, mx0, 2));
            mx0 = fmaxf(mx0, __shfl_xor_sync(0xffffffffu, mx0, 4));
            mx1 = fmaxf(mx1, __shfl_xor_sync(0xffffffffu, mx1, 1));
            mx1 = fmaxf(mx1, __shfl_xor_sync(0xffffffffu, mx1, 2));
            mx1 = fmaxf(mx1, __shfl_xor_sync(0xffffffffu, mx1, 4));

            float mn0 = fmaxf(rowm[2 * i], mx0);
            float mn1 = fmaxf(rowm[2 * i + 1], mx1);
            float al0 = ex2f(rowm[2 * i] - mn0);
            float al1 = ex2f(rowm[2 * i + 1] - mn1);
            rowm[2 * i] = mn0; rowm[2 * i + 1] = mn1;
            ull a0p = pack2(al0, al0), a1p = pack2(al1, al1);
            #pragma unroll
            for (int p = 0; p < 4; p++) {
                Oa[2 * i][p]     = mul2(Oa[2 * i][p], a0p);
                Oa[2 * i + 1][p] = mul2(Oa[2 * i + 1][p], a1p);
            }
            float ps0 = 0.f, ps1 = 0.f;
            #pragma unroll
            for (int j = 0; j < 8; j++) {
                float p0 = ex2f(s0[j] - mn0);
                float p1 = ex2f(s1[j] - mn1);
                ps0 += p0; ps1 += p1;
                KP[R0 * KP_S + tx * 8 + j] = p0;
                KP[R1 * KP_S + tx * 8 + j] = p1;
            }
            rowl[2 * i]     = rowl[2 * i] * al0 + ps0;
            rowl[2 * i + 1] = rowl[2 * i + 1] * al1 + ps1;
        }
        __syncthreads();

        // ---- O += P V : f32x2 paired over d ----
        #pragma unroll 4
        for (int n = 0; n < 64; n++) {
            const ull* vp = (const ull*)(Vs + n * VS_S + tx * 8);
            ull b0 = vp[0], b1 = vp[1], b2 = vp[2], b3 = vp[3];
            #pragma unroll
            for (int r = 0; r < 8; r++) {
                float a = KP[(mrow + r) * KP_S + n];
                ull aa = pack2(a, a);
                fma2(Oa[r][0], aa, b0);
                fma2(Oa[r][1], aa, b1);
                fma2(Oa[r][2], aa, b2);
                fma2(Oa[r][3], aa, b3);
            }
        }
    }

    // ---- finalize: reduce row sums over the 8-lane group, normalize, store ----
    #pragma unroll
    for (int r = 0; r < 8; r++) {
        float l = rowl[r];
        l += __shfl_xor_sync(0xffffffffu, l, 1);
        l += __shfl_xor_sync(0xffffffffu, l, 2);
        l += __shfl_xor_sync(0xffffffffu, l, 4);
        float inv = __fdividef(1.0f, l);
        float x0, x1, x2, x3, x4, x5, x6, x7;
        unpack2(Oa[r][0], x0, x1);
        unpack2(Oa[r][1], x2, x3);
        unpack2(Oa[r][2], x4, x5);
        unpack2(Oa[r][3], x6, x7);
        float* op = oh + (size_t)(m0 + mrow + r) * 1024 + tx * 8;
        *(float4*)op       = make_float4(x0 * inv, x1 * inv, x2 * inv, x3 * inv);
        *(float4*)(op + 4) = make_float4(x4 * inv, x5 * inv, x6 * inv, x7 * inv);
    }
}

extern "C" void kernel_launch(void* const* d_in, const int* in_sizes, int n_in,
                              void* d_out, int out_size)
{
    const float* q   = (const float*)d_in[0];
    const float* k   = (const float*)d_in[1];
    const float* v   = (const float*)d_in[2];
    const float* rph = (const float*)d_in[3];
    const float* rpw = (const float*)d_in[4];
    float* out = (float*)d_out;

    // kernel A: rel logit tables
    dim3 rg(32, 64);
    rel_kernel<<<rg, 256>>>(q, rph, rpw);

    // kernel B: flash attention
    const int smem = (64 * QT_S + 64 * KP_S + 64 * VS_S + 64 * 32 + 64 * 32) * 4; // 67840 B
    cudaFuncSetAttribute(flash_kernel, cudaFuncAttributeMaxDynamicSharedMemorySize, smem);
    dim3 grid(SEQ / 64, NBH);
    flash_kernel<<<grid, 64, smem>>>(q, k, v, out);
}

// round 4
// speedup vs baseline: 1.8081x; 1.8081x over previous
#include <cuda_runtime.h>

typedef unsigned long long ull;

#define SEQ   1024
#define NBH   64
#define LOG2E 1.4426950408889634f

// rel_h / rel_w logit tables, pre-scaled by log2(e): [bh][s][k], k in 0..31
__device__ __align__(16) float g_relH[(size_t)NBH * SEQ * 32];
__device__ __align__(16) float g_relW[(size_t)NBH * SEQ * 32];

// ---------- f32x2 helpers ----------
__device__ __forceinline__ ull pack2(float x, float y) {
    ull r; asm("mov.b64 %0, {%1,%2};" : "=l"(r) : "f"(x), "f"(y)); return r;
}
__device__ __forceinline__ void unpack2(ull p, float& x, float& y) {
    asm("mov.b64 {%0,%1}, %2;" : "=f"(x), "=f"(y) : "l"(p));
}
__device__ __forceinline__ void fma2(ull& d, ull a, ull b) {
    asm("fma.rn.f32x2 %0, %1, %2, %0;" : "+l"(d) : "l"(a), "l"(b));
}
__device__ __forceinline__ ull mul2(ull a, ull b) {
    ull r; asm("mul.rn.f32x2 %0, %1, %2;" : "=l"(r) : "l"(a), "l"(b)); return r;
}
__device__ __forceinline__ float ex2f(float x) {
    float r; asm("ex2.approx.f32 %0, %1;" : "=f"(r) : "f"(x)); return r;
}

// ---------- kernel A: rel_h / rel_w precompute (smem-staged, tiled) ----------
__global__ void __launch_bounds__(256) rel_kernel(
    const float* __restrict__ q,
    const float* __restrict__ rph,
    const float* __restrict__ rpw)
{
    __shared__ float sQ[32 * 68];
    __shared__ float sRh[32 * 68];
    __shared__ float sRw[63 * 68];

    const int tid = threadIdx.x;
    const int h  = blockIdx.x;
    const int bh = blockIdx.y;
    const int b = bh >> 4, hd = bh & 15;

    {
        const int w = tid >> 3, c0 = (tid & 7) * 8;
        const float4* src = (const float4*)(q + ((size_t)(b * SEQ + h * 32 + w) * 16 + hd) * 64 + c0);
        *(float4*)(sQ + w * 68 + c0)     = src[0];
        *(float4*)(sQ + w * 68 + c0 + 4) = src[1];
        const float4* hs = (const float4*)(rph + (size_t)(h + 31 - w) * 64 + c0);
        *(float4*)(sRh + w * 68 + c0)     = hs[0];
        *(float4*)(sRh + w * 68 + c0 + 4) = hs[1];
    }
    for (int i = tid; i < 63 * 16; i += 256) {
        int r = i >> 4, c = (i & 15) * 4;
        *(float4*)(sRw + r * 68 + c) = *(const float4*)(rpw + (size_t)r * 64 + c);
    }
    __syncthreads();

    const int wid = tid >> 5, lane = tid & 31;   // lane = k
    #pragma unroll
    for (int rr = 0; rr < 4; rr++) {
        const int w = wid * 4 + rr;
        const float4* qv = (const float4*)(sQ + w * 68);
        const float4* hv = (const float4*)(sRh + lane * 68);
        const float4* wv = (const float4*)(sRw + (w + 31 - lane) * 68);
        float ah = 0.f, aw = 0.f;
        #pragma unroll
        for (int f = 0; f < 16; f++) {
            float4 a = qv[f], x = hv[f], y = wv[f];
            ah += a.x * x.x + a.y * x.y + a.z * x.z + a.w * x.w;
            aw += a.x * y.x + a.y * y.y + a.z * y.z + a.w * y.w;
        }
        size_t o = ((size_t)bh * SEQ + h * 32 + w) * 32 + lane;
        g_relH[o] = ah * LOG2E;
        g_relW[o] = aw * LOG2E;
    }
}

// ---------- kernel B: fp32 flash attention, conflict-free LDS layouts -------
// block 128 (tx 0..15, ty 0..7); thread tile 8 m-rows x 4 n-cols (n = tx+16j),
// d-cols = {2tx,2tx+1, 2tx+32,2tx+33}. S f32x2-paired over m, O paired over d.
// KP holds K row-major [n][c] during QK (stride 65), then P [m][n] during PV.
#define QT_S 64
#define KP_S 65
#define VS_S 68
#define RL_S 34

__global__ void __launch_bounds__(128, 3)
flash_kernel(const float* __restrict__ q, const float* __restrict__ k,
             const float* __restrict__ v, float* __restrict__ out)
{
    extern __shared__ float sm[];
    float* Qt = sm;                     // [64][64]  Qt[c][m] * 0.125*log2e
    float* KP = Qt + 64 * QT_S;         // [64][65]  K[n][c] in QK, P[m][n] in PV
    float* Vs = KP + 64 * KP_S;         // [64][68]  V[n][d]
    float* rH = Vs + 64 * VS_S;         // [64][34]
    float* rW = rH + 64 * RL_S;         // [64][34]

    const int tid = threadIdx.x;
    const int tx = tid & 15, ty = tid >> 4;
    const int mrow = ty * 8;
    const int m0 = blockIdx.x << 6;
    const int bh = blockIdx.y;
    const int b = bh >> 4, hd = bh & 15;

    const size_t hoff = (size_t)b * SEQ * 1024 + (size_t)hd * 64;
    const float* qh = q + hoff;
    const float* kh = k + hoff;
    const float* vh = v + hoff;
    float*       oh = out + hoff;

    const int lr = tid & 63;            // loader row
    const int lc = (tid >> 6) * 32;     // loader col base

    // ---- load Q tile transposed (scaled) + rel tables ----
    {
        const float qs = 0.125f * LOG2E;
        const float4* src = (const float4*)(qh + (size_t)(m0 + lr) * 1024 + lc);
        #pragma unroll
        for (int f = 0; f < 8; f++) {
            float4 x = src[f];
            const int c = lc + 4 * f;
            Qt[(c + 0) * QT_S + lr] = x.x * qs;
            Qt[(c + 1) * QT_S + lr] = x.y * qs;
            Qt[(c + 2) * QT_S + lr] = x.z * qs;
            Qt[(c + 3) * QT_S + lr] = x.w * qs;
        }
        const float4* rh4 = (const float4*)(g_relH + ((size_t)bh * SEQ + m0) * 32);
        const float4* rw4 = (const float4*)(g_relW + ((size_t)bh * SEQ + m0) * 32);
        #pragma unroll
        for (int f = 0; f < 4; f++) {
            const int gi = tid + f * 128;         // float4 index within 64x32
            const int m = gi >> 3, c4 = (gi & 7) * 4;
            float4 xh = rh4[gi];
            float4 xw = rw4[gi];
            rH[m * RL_S + c4 + 0] = xh.x; rH[m * RL_S + c4 + 1] = xh.y;
            rH[m * RL_S + c4 + 2] = xh.z; rH[m * RL_S + c4 + 3] = xh.w;
            rW[m * RL_S + c4 + 0] = xw.x; rW[m * RL_S + c4 + 1] = xw.y;
            rW[m * RL_S + c4 + 2] = xw.z; rW[m * RL_S + c4 + 3] = xw.w;
        }
    }

    ull   Oa[8][2];                 // 8 m-rows x 2 d-pairs (d=2tx, d=2tx+32)
    float rowm[8], rowl[8];
    #pragma unroll
    for (int r = 0; r < 8; r++) {
        Oa[r][0] = 0ull; Oa[r][1] = 0ull;
        rowm[r] = -3.0e38f; rowl[r] = 0.f;
    }

    for (int n0 = 0; n0 < SEQ; n0 += 64) {
        __syncthreads();   // prev PV done with KP/Vs (iter 0: Qt/rel stores)
        // ---- load K row-major [n][c] (stride 65) + V natural (stride 68) ----
        {
            const float4* ks  = (const float4*)(kh + (size_t)(n0 + lr) * 1024 + lc);
            const float4* vs4 = (const float4*)(vh + (size_t)(n0 + lr) * 1024 + lc);
            float* kd = KP + lr * KP_S + lc;
            float* vd = Vs + lr * VS_S + lc;
            #pragma unroll
            for (int f = 0; f < 8; f++) {
                float4 kx = ks[f];
                kd[4 * f + 0] = kx.x;
                kd[4 * f + 1] = kx.y;
                kd[4 * f + 2] = kx.z;
                kd[4 * f + 3] = kx.w;
                *(float4*)(vd + 4 * f) = vs4[f];
            }
        }
        __syncthreads();

        // ---- S = Qs K^T : 8m x 4n, f32x2 paired over m, conflict-free ----
        ull Sa[4][4];
        #pragma unroll
        for (int i = 0; i < 4; i++)
            #pragma unroll
            for (int j = 0; j < 4; j++) Sa[i][j] = 0ull;

        #pragma unroll 8
        for (int c = 0; c < 64; c++) {
            const ull* qp = (const ull*)(Qt + c * QT_S + mrow);
            ull a0 = qp[0], a1 = qp[1], a2 = qp[2], a3 = qp[3];
            const float* kp = KP + tx * KP_S + c;
            #pragma unroll
            for (int j = 0; j < 4; j++) {
                float bv = kp[16 * j * KP_S];          // K[tx+16j][c]
                ull bb = pack2(bv, bv);
                fma2(Sa[0][j], a0, bb);
                fma2(Sa[1][j], a1, bb);
                fma2(Sa[2][j], a2, bb);
                fma2(Sa[3][j], a3, bb);
            }
        }

        __syncthreads();   // all threads done reading KP as K

        // ---- softmax (2 rows at a time) + P store into KP ----
        const int kh0 = n0 >> 5;
        #pragma unroll
        for (int i = 0; i < 4; i++) {
            float s0[4], s1[4];
            #pragma unroll
            for (int j = 0; j < 4; j++) unpack2(Sa[i][j], s0[j], s1[j]);
            const int R0 = mrow + 2 * i, R1 = R0 + 1;
            // cols j=0..3 -> n = tx+16j: kh = kh0 + (j>=2), kw = tx + 16*(j&1)
            const float rhA0 = rH[R0 * RL_S + kh0],     rhB0 = rH[R0 * RL_S + kh0 + 1];
            const float rhA1 = rH[R1 * RL_S + kh0],     rhB1 = rH[R1 * RL_S + kh0 + 1];
            const float rwA0 = rW[R0 * RL_S + tx],      rwB0 = rW[R0 * RL_S + tx + 16];
            const float rwA1 = rW[R1 * RL_S + tx],      rwB1 = rW[R1 * RL_S + tx + 16];
            s0[0] += rhA0 + rwA0;  s0[1] += rhA0 + rwB0;
            s0[2] += rhB0 + rwA0;  s0[3] += rhB0 + rwB0;
            s1[0] += rhA1 + rwA1;  s1[1] += rhA1 + rwB1;
            s1[2] += rhB1 + rwA1;  s1[3] += rhB1 + rwB1;

            float mx0 = fmaxf(fmaxf(s0[0], s0[1]), fmaxf(s0[2], s0[3]));
            float mx1 = fmaxf(fmaxf(s1[0], s1[1]), fmaxf(s1[2], s1[3]));
            mx0 = fmaxf(mx0, __shfl_xor_sync(0xffffffffu, mx0, 1));
            mx0 = fmaxf(mx0, __shfl_xor_sync(0xffffffffu, mx0, 2));
            mx0 = fmaxf(mx0, __shfl_xor_sync(0xffffffffu, mx0, 4));
            mx0 = fmaxf(mx0, __shfl_xor_sync(0xffffffffu, mx0, 8));
            mx1 = fmaxf(mx1, __shfl_xor_sync(0xffffffffu, mx1, 1));
            mx1 = fmaxf(mx1, __shfl_xor_sync(0xffffffffu, mx1, 2));
            mx1 = fmaxf(mx1, __shfl_xor_sync(0xffffffffu, mx1, 4));
            mx1 = fmaxf(mx1, __shfl_xor_sync(0xffffffffu, mx1, 8));

            float mn0 = fmaxf(rowm[2 * i], mx0);
            float mn1 = fmaxf(rowm[2 * i + 1], mx1);
            float al0 = ex2f(rowm[2 * i] - mn0);
            float al1 = ex2f(rowm[2 * i + 1] - mn1);
            rowm[2 * i] = mn0; rowm[2 * i + 1] = mn1;
            ull a0p = pack2(al0, al0), a1p = pack2(al1, al1);
            Oa[2 * i][0] = mul2(Oa[2 * i][0], a0p);
            Oa[2 * i][1] = mul2(Oa[2 * i][1], a0p);
            Oa[2 * i + 1][0] = mul2(Oa[2 * i + 1][0], a1p);
            Oa[2 * i + 1][1] = mul2(Oa[2 * i + 1][1], a1p);

            float ps0 = 0.f, ps1 = 0.f;
            #pragma unroll
            for (int j = 0; j < 4; j++) {
                float p0 = ex2f(s0[j] - mn0);
                float p1 = ex2f(s1[j] - mn1);
                ps0 += p0; ps1 += p1;
                KP[R0 * KP_S + tx + 16 * j] = p0;
                KP[R1 * KP_S + tx + 16 * j] = p1;
            }
            rowl[2 * i]     = rowl[2 * i] * al0 + ps0;
            rowl[2 * i + 1] = rowl[2 * i + 1] * al1 + ps1;
        }
        __syncthreads();

        // ---- O += P V : d-pairs at 2tx and 2tx+32 ----
        #pragma unroll 8
        for (int n = 0; n < 64; n++) {
            const float* vrow = Vs + n * VS_S + 2 * tx;
            ull b0 = *(const ull*)vrow;
            ull b1 = *(const ull*)(vrow + 32);
            const float* prow = KP + mrow * KP_S + n;
            #pragma unroll
            for (int r = 0; r < 8; r++) {
                float a = prow[r * KP_S];
                ull aa = pack2(a, a);
                fma2(Oa[r][0], aa, b0);
                fma2(Oa[r][1], aa, b1);
            }
        }
    }

    // ---- finalize ----
    #pragma unroll
    for (int r = 0; r < 8; r++) {
        float l = rowl[r];
        l += __shfl_xor_sync(0xffffffffu, l, 1);
        l += __shfl_xor_sync(0xffffffffu, l, 2);
        l += __shfl_xor_sync(0xffffffffu, l, 4);
        l += __shfl_xor_sync(0xffffffffu, l, 8);
        float inv = __fdividef(1.0f, l);
        float x0, x1, x2, x3;
        unpack2(Oa[r][0], x0, x1);
        unpack2(Oa[r][1], x2, x3);
        float* op = oh + (size_t)(m0 + mrow + r) * 1024 + 2 * tx;
        *(float2*)op        = make_float2(x0 * inv, x1 * inv);
        *(float2*)(op + 32) = make_float2(x2 * inv, x3 * inv);
    }
}

extern "C" void kernel_launch(void* const* d_in, const int* in_sizes, int n_in,
                              void* d_out, int out_size)
{
    const float* q   = (const float*)d_in[0];
    const float* k   = (const float*)d_in[1];
    const float* v   = (const float*)d_in[2];
    const float* rph = (const float*)d_in[3];
    const float* rpw = (const float*)d_in[4];
    float* out = (float*)d_out;

    dim3 rg(32, 64);
    rel_kernel<<<rg, 256>>>(q, rph, rpw);

    const int smem = (64 * QT_S + 64 * KP_S + 64 * VS_S + 64 * RL_S * 2) * 4; // 67840 B
    cudaFuncSetAttribute(flash_kernel, cudaFuncAttributeMaxDynamicSharedMemorySize, smem);
    dim3 grid(SEQ / 64, NBH);
    flash_kernel<<<grid, 128, smem>>>(q, k, v, out);
}

// round 5
// speedup vs baseline: 1.8857x; 1.0430x over previous
#include <cuda_runtime.h>

typedef unsigned long long ull;

#define SEQ   1024
#define NBH   64
#define LOG2E 1.4426950408889634f

// rel_h / rel_w logit tables, pre-scaled by log2(e): [bh][s][k], k in 0..31
__device__ __align__(16) float g_relH[(size_t)NBH * SEQ * 32];
__device__ __align__(16) float g_relW[(size_t)NBH * SEQ * 32];

// ---------- f32x2 helpers ----------
__device__ __forceinline__ ull pack2(float x, float y) {
    ull r; asm("mov.b64 %0, {%1,%2};" : "=l"(r) : "f"(x), "f"(y)); return r;
}
__device__ __forceinline__ void unpack2(ull p, float& x, float& y) {
    asm("mov.b64 {%0,%1}, %2;" : "=f"(x), "=f"(y) : "l"(p));
}
__device__ __forceinline__ void fma2(ull& d, ull a, ull b) {
    asm("fma.rn.f32x2 %0, %1, %2, %0;" : "+l"(d) : "l"(a), "l"(b));
}
__device__ __forceinline__ ull mul2(ull a, ull b) {
    ull r; asm("mul.rn.f32x2 %0, %1, %2;" : "=l"(r) : "l"(a), "l"(b)); return r;
}
__device__ __forceinline__ float ex2f(float x) {
    float r; asm("ex2.approx.f32 %0, %1;" : "=f"(r) : "f"(x)); return r;
}

// ---------- kernel A: rel_h / rel_w precompute (smem-staged, tiled) ----------
__global__ void __launch_bounds__(256) rel_kernel(
    const float* __restrict__ q,
    const float* __restrict__ rph,
    const float* __restrict__ rpw)
{
    __shared__ float sQ[32 * 68];
    __shared__ float sRh[32 * 68];
    __shared__ float sRw[63 * 68];

    const int tid = threadIdx.x;
    const int h  = blockIdx.x;
    const int bh = blockIdx.y;
    const int b = bh >> 4, hd = bh & 15;

    {
        const int w = tid >> 3, c0 = (tid & 7) * 8;
        const float4* src = (const float4*)(q + ((size_t)(b * SEQ + h * 32 + w) * 16 + hd) * 64 + c0);
        *(float4*)(sQ + w * 68 + c0)     = src[0];
        *(float4*)(sQ + w * 68 + c0 + 4) = src[1];
        const float4* hs = (const float4*)(rph + (size_t)(h + 31 - w) * 64 + c0);
        *(float4*)(sRh + w * 68 + c0)     = hs[0];
        *(float4*)(sRh + w * 68 + c0 + 4) = hs[1];
    }
    for (int i = tid; i < 63 * 16; i += 256) {
        int r = i >> 4, c = (i & 15) * 4;
        *(float4*)(sRw + r * 68 + c) = *(const float4*)(rpw + (size_t)r * 64 + c);
    }
    __syncthreads();

    const int wid = tid >> 5, lane = tid & 31;   // lane = k
    #pragma unroll
    for (int rr = 0; rr < 4; rr++) {
        const int w = wid * 4 + rr;
        const float4* qv = (const float4*)(sQ + w * 68);
        const float4* hv = (const float4*)(sRh + lane * 68);
        const float4* wv = (const float4*)(sRw + (w + 31 - lane) * 68);
        float ah = 0.f, aw = 0.f;
        #pragma unroll
        for (int f = 0; f < 16; f++) {
            float4 a = qv[f], x = hv[f], y = wv[f];
            ah += a.x * x.x + a.y * x.y + a.z * x.z + a.w * x.w;
            aw += a.x * y.x + a.y * y.y + a.z * y.z + a.w * y.w;
        }
        size_t o = ((size_t)bh * SEQ + h * 32 + w) * 32 + lane;
        g_relH[o] = ah * LOG2E;
        g_relW[o] = aw * LOG2E;
    }
}

// ---------- kernel B: fp32 flash attention ----------
// block 128 (tx 0..15, ty 0..7); thread tile 8 m-rows x 4 n-cols (n = tx+16j),
// d-cols = {2tx,2tx+1, 2tx+32,2tx+33}. S paired over m; O paired over m
// (m-pairs 2i,2i+1); P stored TRANSPOSED Pt[n][m] as ull pairs.
// KP: K[n][c] stride 66 in QK, Pt[n][m] stride 66 in PV.
#define QT_S 64
#define KP_S 66
#define VS_S 68
#define RL_S 34

__global__ void __launch_bounds__(128, 3)
flash_kernel(const float* __restrict__ q, const float* __restrict__ k,
             const float* __restrict__ v, float* __restrict__ out)
{
    extern __shared__ float sm[];
    float* Qt = sm;                     // [64][64]  Qt[c][m] * 0.125*log2e
    float* KP = Qt + 64 * QT_S;         // [64][66]  K[n][c] in QK, Pt[n][m] in PV
    float* Vs = KP + 64 * KP_S;         // [64][68]  V[n][d]
    float* rH = Vs + 64 * VS_S;         // [64][34]
    float* rW = rH + 64 * RL_S;         // [64][34]

    const int tid = threadIdx.x;
    const int tx = tid & 15, ty = tid >> 4;
    const int mrow = ty * 8;
    const int m0 = blockIdx.x << 6;
    const int bh = blockIdx.y;
    const int b = bh >> 4, hd = bh & 15;

    const size_t hoff = (size_t)b * SEQ * 1024 + (size_t)hd * 64;
    const float* qh = q + hoff;
    const float* kh = k + hoff;
    const float* vh = v + hoff;
    float*       oh = out + hoff;

    const int lr = tid & 63;            // loader row
    const int lc = (tid >> 6) * 32;     // loader col base

    // ---- load Q tile transposed (scaled) + rel tables ----
    {
        const float qs = 0.125f * LOG2E;
        const float4* src = (const float4*)(qh + (size_t)(m0 + lr) * 1024 + lc);
        #pragma unroll
        for (int f = 0; f < 8; f++) {
            float4 x = src[f];
            const int c = lc + 4 * f;
            Qt[(c + 0) * QT_S + lr] = x.x * qs;
            Qt[(c + 1) * QT_S + lr] = x.y * qs;
            Qt[(c + 2) * QT_S + lr] = x.z * qs;
            Qt[(c + 3) * QT_S + lr] = x.w * qs;
        }
        const float4* rh4 = (const float4*)(g_relH + ((size_t)bh * SEQ + m0) * 32);
        const float4* rw4 = (const float4*)(g_relW + ((size_t)bh * SEQ + m0) * 32);
        #pragma unroll
        for (int f = 0; f < 4; f++) {
            const int gi = tid + f * 128;         // float4 index within 64x32
            const int m = gi >> 3, c4 = (gi & 7) * 4;
            float4 xh = rh4[gi];
            float4 xw = rw4[gi];
            rH[m * RL_S + c4 + 0] = xh.x; rH[m * RL_S + c4 + 1] = xh.y;
            rH[m * RL_S + c4 + 2] = xh.z; rH[m * RL_S + c4 + 3] = xh.w;
            rW[m * RL_S + c4 + 0] = xw.x; rW[m * RL_S + c4 + 1] = xw.y;
            rW[m * RL_S + c4 + 2] = xw.z; rW[m * RL_S + c4 + 3] = xw.w;
        }
    }

    // O accumulator: Om[mpair i][d-index u], ull lanes = rows (2i, 2i+1)
    // u: 0 -> d=2tx, 1 -> 2tx+1, 2 -> 2tx+32, 3 -> 2tx+33
    ull   Om[4][4];
    float rowm[8], rowl[8];
    #pragma unroll
    for (int i = 0; i < 4; i++) {
        Om[i][0] = 0ull; Om[i][1] = 0ull; Om[i][2] = 0ull; Om[i][3] = 0ull;
    }
    #pragma unroll
    for (int r = 0; r < 8; r++) { rowm[r] = -3.0e38f; rowl[r] = 0.f; }

    for (int n0 = 0; n0 < SEQ; n0 += 64) {
        __syncthreads();   // prev PV done with KP/Vs (iter 0: Qt/rel stores)
        // ---- load K row-major [n][c] (stride 66) + V natural (stride 68) ----
        {
            const float4* ks  = (const float4*)(kh + (size_t)(n0 + lr) * 1024 + lc);
            const float4* vs4 = (const float4*)(vh + (size_t)(n0 + lr) * 1024 + lc);
            float* kd = KP + lr * KP_S + lc;
            float* vd = Vs + lr * VS_S + lc;
            #pragma unroll
            for (int f = 0; f < 8; f++) {
                float4 kx = ks[f];
                *(float2*)(kd + 4 * f)     = make_float2(kx.x, kx.y);
                *(float2*)(kd + 4 * f + 2) = make_float2(kx.z, kx.w);
                *(float4*)(vd + 4 * f) = vs4[f];
            }
        }
        __syncthreads();

        // ---- S = Qs K^T : 8m x 4n, f32x2 paired over m ----
        ull Sa[4][4];
        #pragma unroll
        for (int i = 0; i < 4; i++)
            #pragma unroll
            for (int j = 0; j < 4; j++) Sa[i][j] = 0ull;

        #pragma unroll 8
        for (int c = 0; c < 64; c++) {
            const ulonglong2* qp = (const ulonglong2*)(Qt + c * QT_S + mrow);
            ulonglong2 qA = qp[0], qB = qp[1];
            const float* kp = KP + tx * KP_S + c;
            #pragma unroll
            for (int j = 0; j < 4; j++) {
                float bv = kp[16 * j * KP_S];          // K[tx+16j][c]
                ull bb = pack2(bv, bv);
                fma2(Sa[0][j], qA.x, bb);
                fma2(Sa[1][j], qA.y, bb);
                fma2(Sa[2][j], qB.x, bb);
                fma2(Sa[3][j], qB.y, bb);
            }
        }

        __syncthreads();   // all threads done reading KP as K

        // ---- softmax (2 rows at a time) + Pt store (transposed, ull pairs) ----
        const int kh0 = n0 >> 5;
        #pragma unroll
        for (int i = 0; i < 4; i++) {
            float s0[4], s1[4];
            #pragma unroll
            for (int j = 0; j < 4; j++) unpack2(Sa[i][j], s0[j], s1[j]);
            const int R0 = mrow + 2 * i, R1 = R0 + 1;
            // cols j=0..3 -> n = tx+16j: kh = kh0 + (j>=2), kw = tx + 16*(j&1)
            const float rhA0 = rH[R0 * RL_S + kh0],     rhB0 = rH[R0 * RL_S + kh0 + 1];
            const float rhA1 = rH[R1 * RL_S + kh0],     rhB1 = rH[R1 * RL_S + kh0 + 1];
            const float rwA0 = rW[R0 * RL_S + tx],      rwB0 = rW[R0 * RL_S + tx + 16];
            const float rwA1 = rW[R1 * RL_S + tx],      rwB1 = rW[R1 * RL_S + tx + 16];
            s0[0] += rhA0 + rwA0;  s0[1] += rhA0 + rwB0;
            s0[2] += rhB0 + rwA0;  s0[3] += rhB0 + rwB0;
            s1[0] += rhA1 + rwA1;  s1[1] += rhA1 + rwB1;
            s1[2] += rhB1 + rwA1;  s1[3] += rhB1 + rwB1;

            float mx0 = fmaxf(fmaxf(s0[0], s0[1]), fmaxf(s0[2], s0[3]));
            float mx1 = fmaxf(fmaxf(s1[0], s1[1]), fmaxf(s1[2], s1[3]));
            mx0 = fmaxf(mx0, __shfl_xor_sync(0xffffffffu, mx0, 1));
            mx0 = fmaxf(mx0, __shfl_xor_sync(0xffffffffu, mx0, 2));
            mx0 = fmaxf(mx0, __shfl_xor_sync(0xffffffffu, mx0, 4));
            mx0 = fmaxf(mx0, __shfl_xor_sync(0xffffffffu, mx0, 8));
            mx1 = fmaxf(mx1, __shfl_xor_sync(0xffffffffu, mx1, 1));
            mx1 = fmaxf(mx1, __shfl_xor_sync(0xffffffffu, mx1, 2));
            mx1 = fmaxf(mx1, __shfl_xor_sync(0xffffffffu, mx1, 4));
            mx1 = fmaxf(mx1, __shfl_xor_sync(0xffffffffu, mx1, 8));

            float mn0 = fmaxf(rowm[2 * i], mx0);
            float mn1 = fmaxf(rowm[2 * i + 1], mx1);
            float al0 = ex2f(rowm[2 * i] - mn0);
            float al1 = ex2f(rowm[2 * i + 1] - mn1);
            rowm[2 * i] = mn0; rowm[2 * i + 1] = mn1;
            ull alp = pack2(al0, al1);
            Om[i][0] = mul2(Om[i][0], alp);
            Om[i][1] = mul2(Om[i][1], alp);
            Om[i][2] = mul2(Om[i][2], alp);
            Om[i][3] = mul2(Om[i][3], alp);

            float ps0 = 0.f, ps1 = 0.f;
            #pragma unroll
            for (int j = 0; j < 4; j++) {
                float p0 = ex2f(s0[j] - mn0);
                float p1 = ex2f(s1[j] - mn1);
                ps0 += p0; ps1 += p1;
                *(ull*)(KP + (tx + 16 * j) * KP_S + R0) = pack2(p0, p1);
            }
            rowl[2 * i]     = rowl[2 * i] * al0 + ps0;
            rowl[2 * i + 1] = rowl[2 * i + 1] * al1 + ps1;
        }
        __syncthreads();

        // ---- O += P V : O paired over m, Pt broadcast reads ----
        #pragma unroll 8
        for (int n = 0; n < 64; n++) {
            const float* vrow = Vs + n * VS_S + 2 * tx;
            float v0, v1, v2, v3;
            unpack2(*(const ull*)vrow,        v0, v1);
            unpack2(*(const ull*)(vrow + 32), v2, v3);
            ull d0 = pack2(v0, v0), d1 = pack2(v1, v1);
            ull d2 = pack2(v2, v2), d3 = pack2(v3, v3);
            const ull* pp = (const ull*)(KP + n * KP_S + mrow);
            ull p0 = pp[0], p1 = pp[1], p2 = pp[2], p3 = pp[3];
            fma2(Om[0][0], p0, d0); fma2(Om[0][1], p0, d1);
            fma2(Om[0][2], p0, d2); fma2(Om[0][3], p0, d3);
            fma2(Om[1][0], p1, d0); fma2(Om[1][1], p1, d1);
            fma2(Om[1][2], p1, d2); fma2(Om[1][3], p1, d3);
            fma2(Om[2][0], p2, d0); fma2(Om[2][1], p2, d1);
            fma2(Om[2][2], p2, d2); fma2(Om[2][3], p2, d3);
            fma2(Om[3][0], p3, d0); fma2(Om[3][1], p3, d1);
            fma2(Om[3][2], p3, d2); fma2(Om[3][3], p3, d3);
        }
    }

    // ---- finalize ----
    #pragma unroll
    for (int r = 0; r < 8; r++) {
        float l = rowl[r];
        l += __shfl_xor_sync(0xffffffffu, l, 1);
        l += __shfl_xor_sync(0xffffffffu, l, 2);
        l += __shfl_xor_sync(0xffffffffu, l, 4);
        l += __shfl_xor_sync(0xffffffffu, l, 8);
        rowl[r] = __fdividef(1.0f, l);
    }
    #pragma unroll
    for (int i = 0; i < 4; i++) {
        const float inv0 = rowl[2 * i], inv1 = rowl[2 * i + 1];
        float o00, o10, o01, o11, o02, o12, o03, o13;
        unpack2(Om[i][0], o00, o10);
        unpack2(Om[i][1], o01, o11);
        unpack2(Om[i][2], o02, o12);
        unpack2(Om[i][3], o03, o13);
        float* op0 = oh + (size_t)(m0 + mrow + 2 * i) * 1024 + 2 * tx;
        float* op1 = op0 + 1024;
        *(float2*)op0        = make_float2(o00 * inv0, o01 * inv0);
        *(float2*)(op0 + 32) = make_float2(o02 * inv0, o03 * inv0);
        *(float2*)op1        = make_float2(o10 * inv1, o11 * inv1);
        *(float2*)(op1 + 32) = make_float2(o12 * inv1, o13 * inv1);
    }
}

extern "C" void kernel_launch(void* const* d_in, const int* in_sizes, int n_in,
                              void* d_out, int out_size)
{
    const float* q   = (const float*)d_in[0];
    const float* k   = (const float*)d_in[1];
    const float* v   = (const float*)d_in[2];
    const float* rph = (const float*)d_in[3];
    const float* rpw = (const float*)d_in[4];
    float* out = (float*)d_out;

    dim3 rg(32, 64);
    rel_kernel<<<rg, 256>>>(q, rph, rpw);

    const int smem = (64 * QT_S + 64 * KP_S + 64 * VS_S + 64 * RL_S * 2) * 4; // 68096 B
    cudaFuncSetAttribute(flash_kernel, cudaFuncAttributeMaxDynamicSharedMemorySize, smem);
    dim3 grid(SEQ / 64, NBH);
    flash_kernel<<<grid, 128, smem>>>(q, k, v, out);
}

// round 6
// speedup vs baseline: 1.8887x; 1.0016x over previous
#include <cuda_runtime.h>

typedef unsigned long long ull;

#define SEQ   1024
#define NBH   64
#define LOG2E 1.4426950408889634f

// rel_h / rel_w logit tables, pre-scaled by log2(e): [bh][s][k], k in 0..31
__device__ __align__(16) float g_relH[(size_t)NBH * SEQ * 32];
__device__ __align__(16) float g_relW[(size_t)NBH * SEQ * 32];

// ---------- f32x2 helpers ----------
__device__ __forceinline__ ull pack2(float x, float y) {
    ull r; asm("mov.b64 %0, {%1,%2};" : "=l"(r) : "f"(x), "f"(y)); return r;
}
__device__ __forceinline__ void unpack2(ull p, float& x, float& y) {
    asm("mov.b64 {%0,%1}, %2;" : "=f"(x), "=f"(y) : "l"(p));
}
__device__ __forceinline__ void fma2(ull& d, ull a, ull b) {
    asm("fma.rn.f32x2 %0, %1, %2, %0;" : "+l"(d) : "l"(a), "l"(b));
}
__device__ __forceinline__ ull mul2(ull a, ull b) {
    ull r; asm("mul.rn.f32x2 %0, %1, %2;" : "=l"(r) : "l"(a), "l"(b)); return r;
}
__device__ __forceinline__ float ex2f(float x) {
    float r; asm("ex2.approx.f32 %0, %1;" : "=f"(r) : "f"(x)); return r;
}

// ---------- kernel A: rel_h / rel_w precompute (smem-staged, tiled) ----------
__global__ void __launch_bounds__(256) rel_kernel(
    const float* __restrict__ q,
    const float* __restrict__ rph,
    const float* __restrict__ rpw)
{
    __shared__ float sQ[32 * 68];
    __shared__ float sRh[32 * 68];
    __shared__ float sRw[63 * 68];

    const int tid = threadIdx.x;
    const int h  = blockIdx.x;
    const int bh = blockIdx.y;
    const int b = bh >> 4, hd = bh & 15;

    {
        const int w = tid >> 3, c0 = (tid & 7) * 8;
        const float4* src = (const float4*)(q + ((size_t)(b * SEQ + h * 32 + w) * 16 + hd) * 64 + c0);
        *(float4*)(sQ + w * 68 + c0)     = src[0];
        *(float4*)(sQ + w * 68 + c0 + 4) = src[1];
        const float4* hs = (const float4*)(rph + (size_t)(h + 31 - w) * 64 + c0);
        *(float4*)(sRh + w * 68 + c0)     = hs[0];
        *(float4*)(sRh + w * 68 + c0 + 4) = hs[1];
    }
    for (int i = tid; i < 63 * 16; i += 256) {
        int r = i >> 4, c = (i & 15) * 4;
        *(float4*)(sRw + r * 68 + c) = *(const float4*)(rpw + (size_t)r * 64 + c);
    }
    __syncthreads();

    const int wid = tid >> 5, lane = tid & 31;   // lane = k
    #pragma unroll
    for (int rr = 0; rr < 4; rr++) {
        const int w = wid * 4 + rr;
        const float4* qv = (const float4*)(sQ + w * 68);
        const float4* hv = (const float4*)(sRh + lane * 68);
        const float4* wv = (const float4*)(sRw + (w + 31 - lane) * 68);
        float ah = 0.f, aw = 0.f;
        #pragma unroll
        for (int f = 0; f < 16; f++) {
            float4 a = qv[f], x = hv[f], y = wv[f];
            ah += a.x * x.x + a.y * x.y + a.z * x.z + a.w * x.w;
            aw += a.x * y.x + a.y * y.y + a.z * y.z + a.w * y.w;
        }
        size_t o = ((size_t)bh * SEQ + h * 32 + w) * 32 + lane;
        g_relH[o] = ah * LOG2E;
        g_relW[o] = aw * LOG2E;
    }
}

// ---------- kernel B: fp32 flash attention ----------
// block 128 (tx 0..15, ty 0..7); thread tile 8 m-rows x 4 n-cols (n = tx+16j),
// d-cols = {2tx,2tx+1, 2tx+32,2tx+33}. S paired over m; O paired over m
// (m-pairs 2i,2i+1); P stored TRANSPOSED Pt[n][m] as ull pairs.
// KP: K[n][c] stride 66 in QK, Pt[n][m] stride 66 in PV.
#define QT_S 64
#define KP_S 66
#define VS_S 68
#define RL_S 34

__global__ void __launch_bounds__(128, 3)
flash_kernel(const float* __restrict__ q, const float* __restrict__ k,
             const float* __restrict__ v, float* __restrict__ out)
{
    extern __shared__ float sm[];
    float* Qt = sm;                     // [64][64]  Qt[c][m] * 0.125*log2e
    float* KP = Qt + 64 * QT_S;         // [64][66]  K[n][c] in QK, Pt[n][m] in PV
    float* Vs = KP + 64 * KP_S;         // [64][68]  V[n][d]
    float* rH = Vs + 64 * VS_S;         // [64][34]
    float* rW = rH + 64 * RL_S;         // [64][34]

    const int tid = threadIdx.x;
    const int tx = tid & 15, ty = tid >> 4;
    const int mrow = ty * 8;
    const int m0 = blockIdx.x << 6;
    const int bh = blockIdx.y;
    const int b = bh >> 4, hd = bh & 15;

    const size_t hoff = (size_t)b * SEQ * 1024 + (size_t)hd * 64;
    const float* qh = q + hoff;
    const float* kh = k + hoff;
    const float* vh = v + hoff;
    float*       oh = out + hoff;

    const int lr = tid & 63;            // loader row
    const int lc = (tid >> 6) * 32;     // loader col base

    // ---- load Q tile transposed (scaled) + rel tables ----
    {
        const float qs = 0.125f * LOG2E;
        const float4* src = (const float4*)(qh + (size_t)(m0 + lr) * 1024 + lc);
        #pragma unroll
        for (int f = 0; f < 8; f++) {
            float4 x = src[f];
            const int c = lc + 4 * f;
            Qt[(c + 0) * QT_S + lr] = x.x * qs;
            Qt[(c + 1) * QT_S + lr] = x.y * qs;
            Qt[(c + 2) * QT_S + lr] = x.z * qs;
            Qt[(c + 3) * QT_S + lr] = x.w * qs;
        }
        const float4* rh4 = (const float4*)(g_relH + ((size_t)bh * SEQ + m0) * 32);
        const float4* rw4 = (const float4*)(g_relW + ((size_t)bh * SEQ + m0) * 32);
        #pragma unroll
        for (int f = 0; f < 4; f++) {
            const int gi = tid + f * 128;         // float4 index within 64x32
            const int m = gi >> 3, c4 = (gi & 7) * 4;
            float4 xh = rh4[gi];
            float4 xw = rw4[gi];
            rH[m * RL_S + c4 + 0] = xh.x; rH[m * RL_S + c4 + 1] = xh.y;
            rH[m * RL_S + c4 + 2] = xh.z; rH[m * RL_S + c4 + 3] = xh.w;
            rW[m * RL_S + c4 + 0] = xw.x; rW[m * RL_S + c4 + 1] = xw.y;
            rW[m * RL_S + c4 + 2] = xw.z; rW[m * RL_S + c4 + 3] = xw.w;
        }
    }

    // O accumulator: Om[mpair i][d-index u], ull lanes = rows (2i, 2i+1)
    // u: 0 -> d=2tx, 1 -> 2tx+1, 2 -> 2tx+32, 3 -> 2tx+33
    ull   Om[4][4];
    float rowm[8], rowl[8];
    #pragma unroll
    for (int i = 0; i < 4; i++) {
        Om[i][0] = 0ull; Om[i][1] = 0ull; Om[i][2] = 0ull; Om[i][3] = 0ull;
    }
    #pragma unroll
    for (int r = 0; r < 8; r++) { rowm[r] = -3.0e38f; rowl[r] = 0.f; }

    for (int n0 = 0; n0 < SEQ; n0 += 64) {
        __syncthreads();   // prev PV done with KP/Vs (iter 0: Qt/rel stores)
        // ---- load K row-major [n][c] (stride 66) + V natural (stride 68) ----
        {
            const float4* ks  = (const float4*)(kh + (size_t)(n0 + lr) * 1024 + lc);
            const float4* vs4 = (const float4*)(vh + (size_t)(n0 + lr) * 1024 + lc);
            float* kd = KP + lr * KP_S + lc;
            float* vd = Vs + lr * VS_S + lc;
            #pragma unroll
            for (int f = 0; f < 8; f++) {
                float4 kx = ks[f];
                *(float2*)(kd + 4 * f)     = make_float2(kx.x, kx.y);
                *(float2*)(kd + 4 * f + 2) = make_float2(kx.z, kx.w);
                *(float4*)(vd + 4 * f) = vs4[f];
            }
        }
        __syncthreads();

        // ---- S = Qs K^T : 8m x 4n, f32x2 paired over m ----
        ull Sa[4][4];
        #pragma unroll
        for (int i = 0; i < 4; i++)
            #pragma unroll
            for (int j = 0; j < 4; j++) Sa[i][j] = 0ull;

        #pragma unroll 8
        for (int c = 0; c < 64; c++) {
            const ulonglong2* qp = (const ulonglong2*)(Qt + c * QT_S + mrow);
            ulonglong2 qA = qp[0], qB = qp[1];
            const float* kp = KP + tx * KP_S + c;
            #pragma unroll
            for (int j = 0; j < 4; j++) {
                float bv = kp[16 * j * KP_S];          // K[tx+16j][c]
                ull bb = pack2(bv, bv);
                fma2(Sa[0][j], qA.x, bb);
                fma2(Sa[1][j], qA.y, bb);
                fma2(Sa[2][j], qB.x, bb);
                fma2(Sa[3][j], qB.y, bb);
            }
        }

        __syncthreads();   // all threads done reading KP as K

        // ---- softmax (2 rows at a time) + Pt store (transposed, ull pairs) ----
        const int kh0 = n0 >> 5;
        #pragma unroll
        for (int i = 0; i < 4; i++) {
            float s0[4], s1[4];
            #pragma unroll
            for (int j = 0; j < 4; j++) unpack2(Sa[i][j], s0[j], s1[j]);
            const int R0 = mrow + 2 * i, R1 = R0 + 1;
            // cols j=0..3 -> n = tx+16j: kh = kh0 + (j>=2), kw = tx + 16*(j&1)
            const float rhA0 = rH[R0 * RL_S + kh0],     rhB0 = rH[R0 * RL_S + kh0 + 1];
            const float rhA1 = rH[R1 * RL_S + kh0],     rhB1 = rH[R1 * RL_S + kh0 + 1];
            const float rwA0 = rW[R0 * RL_S + tx],      rwB0 = rW[R0 * RL_S + tx + 16];
            const float rwA1 = rW[R1 * RL_S + tx],      rwB1 = rW[R1 * RL_S + tx + 16];
            s0[0] += rhA0 + rwA0;  s0[1] += rhA0 + rwB0;
            s0[2] += rhB0 + rwA0;  s0[3] += rhB0 + rwB0;
            s1[0] += rhA1 + rwA1;  s1[1] += rhA1 + rwB1;
            s1[2] += rhB1 + rwA1;  s1[3] += rhB1 + rwB1;

            float mx0 = fmaxf(fmaxf(s0[0], s0[1]), fmaxf(s0[2], s0[3]));
            float mx1 = fmaxf(fmaxf(s1[0], s1[1]), fmaxf(s1[2], s1[3]));
            mx0 = fmaxf(mx0, __shfl_xor_sync(0xffffffffu, mx0, 1));
            mx0 = fmaxf(mx0, __shfl_xor_sync(0xffffffffu, mx0, 2));
            mx0 = fmaxf(mx0, __shfl_xor_sync(0xffffffffu, mx0, 4));
            mx0 = fmaxf(mx0, __shfl_xor_sync(0xffffffffu, mx0, 8));
            mx1 = fmaxf(mx1, __shfl_xor_sync(0xffffffffu, mx1, 1));
            mx1 = fmaxf(mx1, __shfl_xor_sync(0xffffffffu, mx1, 2));
            mx1 = fmaxf(mx1, __shfl_xor_sync(0xffffffffu, mx1, 4));
            mx1 = fmaxf(mx1, __shfl_xor_sync(0xffffffffu, mx1, 8));

            float mn0 = fmaxf(rowm[2 * i], mx0);
            float mn1 = fmaxf(rowm[2 * i + 1], mx1);
            float al0 = ex2f(rowm[2 * i] - mn0);
            float al1 = ex2f(rowm[2 * i + 1] - mn1);
            rowm[2 * i] = mn0; rowm[2 * i + 1] = mn1;
            ull alp = pack2(al0, al1);
            Om[i][0] = mul2(Om[i][0], alp);
            Om[i][1] = mul2(Om[i][1], alp);
            Om[i][2] = mul2(Om[i][2], alp);
            Om[i][3] = mul2(Om[i][3], alp);

            float ps0 = 0.f, ps1 = 0.f;
            #pragma unroll
            for (int j = 0; j < 4; j++) {
                float p0 = ex2f(s0[j] - mn0);
                float p1 = ex2f(s1[j] - mn1);
                ps0 += p0; ps1 += p1;
                *(ull*)(KP + (tx + 16 * j) * KP_S + R0) = pack2(p0, p1);
            }
            rowl[2 * i]     = rowl[2 * i] * al0 + ps0;
            rowl[2 * i + 1] = rowl[2 * i + 1] * al1 + ps1;
        }
        __syncthreads();

        // ---- O += P V : O paired over m, Pt broadcast reads ----
        #pragma unroll 8
        for (int n = 0; n < 64; n++) {
            const float* vrow = Vs + n * VS_S + 2 * tx;
            float v0, v1, v2, v3;
            unpack2(*(const ull*)vrow,        v0, v1);
            unpack2(*(const ull*)(vrow + 32), v2, v3);
            ull d0 = pack2(v0, v0), d1 = pack2(v1, v1);
            ull d2 = pack2(v2, v2), d3 = pack2(v3, v3);
            const ull* pp = (const ull*)(KP + n * KP_S + mrow);
            ull p0 = pp[0], p1 = pp[1], p2 = pp[2], p3 = pp[3];
            fma2(Om[0][0], p0, d0); fma2(Om[0][1], p0, d1);
            fma2(Om[0][2], p0, d2); fma2(Om[0][3], p0, d3);
            fma2(Om[1][0], p1, d0); fma2(Om[1][1], p1, d1);
            fma2(Om[1][2], p1, d2); fma2(Om[1][3], p1, d3);
            fma2(Om[2][0], p2, d0); fma2(Om[2][1], p2, d1);
            fma2(Om[2][2], p2, d2); fma2(Om[2][3], p2, d3);
            fma2(Om[3][0], p3, d0); fma2(Om[3][1], p3, d1);
            fma2(Om[3][2], p3, d2); fma2(Om[3][3], p3, d3);
        }
    }

    // ---- finalize ----
    #pragma unroll
    for (int r = 0; r < 8; r++) {
        float l = rowl[r];
        l += __shfl_xor_sync(0xffffffffu, l, 1);
        l += __shfl_xor_sync(0xffffffffu, l, 2);
        l += __shfl_xor_sync(0xffffffffu, l, 4);
        l += __shfl_xor_sync(0xffffffffu, l, 8);
        rowl[r] = __fdividef(1.0f, l);
    }
    #pragma unroll
    for (int i = 0; i < 4; i++) {
        const float inv0 = rowl[2 * i], inv1 = rowl[2 * i + 1];
        float o00, o10, o01, o11, o02, o12, o03, o13;
        unpack2(Om[i][0], o00, o10);
        unpack2(Om[i][1], o01, o11);
        unpack2(Om[i][2], o02, o12);
        unpack2(Om[i][3], o03, o13);
        float* op0 = oh + (size_t)(m0 + mrow + 2 * i) * 1024 + 2 * tx;
        float* op1 = op0 + 1024;
        *(float2*)op0        = make_float2(o00 * inv0, o01 * inv0);
        *(float2*)(op0 + 32) = make_float2(o02 * inv0, o03 * inv0);
        *(float2*)op1        = make_float2(o10 * inv1, o11 * inv1);
        *(float2*)(op1 + 32) = make_float2(o12 * inv1, o13 * inv1);
    }
}

extern "C" void kernel_launch(void* const* d_in, const int* in_sizes, int n_in,
                              void* d_out, int out_size)
{
    const float* q   = (const float*)d_in[0];
    const float* k   = (const float*)d_in[1];
    const float* v   = (const float*)d_in[2];
    const float* rph = (const float*)d_in[3];
    const float* rpw = (const float*)d_in[4];
    float* out = (float*)d_out;

    dim3 rg(32, 64);
    rel_kernel<<<rg, 256>>>(q, rph, rpw);

    const int smem = (64 * QT_S + 64 * KP_S + 64 * VS_S + 64 * RL_S * 2) * 4; // 68096 B
    cudaFuncSetAttribute(flash_kernel, cudaFuncAttributeMaxDynamicSharedMemorySize, smem);
    dim3 grid(SEQ / 64, NBH);
    flash_kernel<<<grid, 128, smem>>>(q, k, v, out);
}